// round 2
// baseline (speedup 1.0000x reference)
#include <cuda_runtime.h>
#include <cstddef>

#define N_NODES 50000
#define N_EDGES 800000

// ---------------- scratch (static device arrays; no allocation) ----------------
__device__ __align__(16) float g_bufA[N_NODES * 128];
__device__ __align__(16) float g_bufB[N_NODES * 128];
__device__ float g_dinv[N_NODES];
__device__ int   g_cnt[N_NODES];
__device__ int   g_off[N_NODES + 1];
__device__ int   g_cur[N_NODES];
__device__ int   g_col[N_EDGES];
__device__ int   g_is32;

// ---------------- packed f32x2 helpers (Blackwell) ----------------
__device__ __forceinline__ unsigned long long fma2(unsigned long long a,
                                                   unsigned long long b,
                                                   unsigned long long c) {
    unsigned long long d;
    asm("fma.rn.f32x2 %0, %1, %2, %3;" : "=l"(d) : "l"(a), "l"(b), "l"(c));
    return d;
}
__device__ __forceinline__ unsigned long long pack2(float x, float y) {
    unsigned long long d;
    asm("mov.b64 %0, {%1, %2};" : "=l"(d) : "f"(x), "f"(y));
    return d;
}

// edge accessor: handles int32 vs int64 storage (flag set by k_detect)
__device__ __forceinline__ int edge_at(const void* ei, size_t idx) {
    if (g_is32) return ((const int*)ei)[idx];
    return (int)((const long long*)ei)[idx];
}

// ---------------- dtype detection ----------------
// If stored int32, an int64-interpreted word packs two random values in
// [0, 50000): high half nonzero w.h.p. => value >= 2^32. Under true int64 all
// values < N_NODES. Reading first 64 int64 words is in-bounds either way
// (int32 array = 800000 int64 words; int64 array = 1.6M words).
__global__ void k_detect(const long long* __restrict__ ei64) {
    int is32 = 0;
    for (int i = 0; i < 64; i++) {
        long long v = ei64[i];
        if (v < 0 || v >= N_NODES) { is32 = 1; break; }
    }
    g_is32 = is32;
}

// ---------------- graph prep ----------------
__global__ void k_zero() {
    int i = blockIdx.x * blockDim.x + threadIdx.x;
    if (i < N_NODES) g_cnt[i] = 0;
}

__global__ void k_count(const void* __restrict__ ei) {
    int e = blockIdx.x * blockDim.x + threadIdx.x;
    if (e < N_EDGES) {
        int dst = edge_at(ei, (size_t)N_EDGES + e);
        atomicAdd(&g_cnt[dst], 1);
    }
}

__global__ void k_dinv() {
    int i = blockIdx.x * blockDim.x + threadIdx.x;
    if (i < N_NODES) g_dinv[i] = rsqrtf((float)g_cnt[i] + 1.0f);  // +1 = self loop
}

// single-block exclusive scan of g_cnt -> g_off (and g_cur copy)
__global__ void k_scan() {
    __shared__ int sm[1024];
    __shared__ int carry;
    int tid = threadIdx.x;
    if (tid == 0) carry = 0;
    __syncthreads();
    for (int base = 0; base < N_NODES; base += 1024) {
        int i = base + tid;
        int v = (i < N_NODES) ? g_cnt[i] : 0;
        sm[tid] = v;
        __syncthreads();
        for (int s = 1; s < 1024; s <<= 1) {
            int t = (tid >= s) ? sm[tid - s] : 0;
            __syncthreads();
            sm[tid] += t;
            __syncthreads();
        }
        if (i < N_NODES) {
            int o = carry + sm[tid] - v;  // exclusive
            g_off[i] = o;
            g_cur[i] = o;
        }
        __syncthreads();
        if (tid == 1023) carry += sm[1023];
        __syncthreads();
    }
    if (tid == 0) g_off[N_NODES] = carry;
}

__global__ void k_scatter(const void* __restrict__ ei) {
    int e = blockIdx.x * blockDim.x + threadIdx.x;
    if (e < N_EDGES) {
        int src = edge_at(ei, (size_t)e);
        int dst = edge_at(ei, (size_t)N_EDGES + e);
        int pos = atomicAdd(&g_cur[dst], 1);
        g_col[pos] = src;
    }
}

// ---------------- GEMM: U = dinv .* (A @ W) ----------------
// A: [N_NODES, 128] row-major. W: [128, ncols]. U: [N_NODES, ncols].
// Tile BM=128, BN=64, BK=32. 256 threads, each computes 8 rows x 4 cols
// using packed f32x2 FMA (row-pairs packed).
__global__ void k_gemm(const float* __restrict__ A, const float* __restrict__ W,
                       float* __restrict__ U, int ncols) {
    __shared__ __align__(16) float As[32 * 128];  // transposed: As[k*128 + m]
    __shared__ __align__(16) float Ws[32 * 64];   // Ws[k*64 + n]
    int tid = threadIdx.x;
    int tx = tid & 15;   // 0..15 -> 4 cols each
    int ty = tid >> 4;   // 0..15 -> 8 rows each
    int row0 = blockIdx.x * 128;
    int col0 = blockIdx.y * 64;

    unsigned long long acc[4][4];   // [row-pair][col], pair p = rows {2p, 2p+1} of this thread
#pragma unroll
    for (int p = 0; p < 4; p++)
#pragma unroll
        for (int j = 0; j < 4; j++) acc[p][j] = 0ULL;

    for (int kt = 0; kt < 128; kt += 32) {
        // load A tile (128 rows x 32 k), transpose into As
#pragma unroll
        for (int j = 0; j < 4; j++) {
            int f = tid + 256 * j;       // 0..1023 float4 slots
            int r = f >> 3;              // 0..127 row within tile
            int kc = (f & 7) << 2;       // 0,4,...,28
            int row = row0 + r;
            float4 v = make_float4(0.f, 0.f, 0.f, 0.f);
            if (row < N_NODES)
                v = *(const float4*)&A[(size_t)row * 128 + kt + kc];
            As[(kc + 0) * 128 + r] = v.x;
            As[(kc + 1) * 128 + r] = v.y;
            As[(kc + 2) * 128 + r] = v.z;
            As[(kc + 3) * 128 + r] = v.w;
        }
        // load W tile (32 k x 64 cols)
#pragma unroll
        for (int j = 0; j < 2; j++) {
            int f = tid + 256 * j;       // 0..511 float4 slots
            int kr = f >> 4;             // 0..31
            int cc = (f & 15) << 2;      // 0..60
            *(float4*)&Ws[kr * 64 + cc] =
                *(const float4*)&W[(size_t)(kt + kr) * ncols + col0 + cc];
        }
        __syncthreads();

#pragma unroll
        for (int k = 0; k < 32; k++) {
            ulonglong2 a01 = *(const ulonglong2*)&As[k * 128 + ty * 8];
            ulonglong2 a23 = *(const ulonglong2*)&As[k * 128 + ty * 8 + 4];
            float4 bv = *(const float4*)&Ws[k * 64 + tx * 4];
            unsigned long long av[4] = {a01.x, a01.y, a23.x, a23.y};
            unsigned long long bb[4] = {pack2(bv.x, bv.x), pack2(bv.y, bv.y),
                                        pack2(bv.z, bv.z), pack2(bv.w, bv.w)};
#pragma unroll
            for (int p = 0; p < 4; p++)
#pragma unroll
                for (int j = 0; j < 4; j++)
                    acc[p][j] = fma2(av[p], bb[j], acc[p][j]);
        }
        __syncthreads();
    }

    // epilogue: scale each row by dinv[row], write U
#pragma unroll
    for (int p = 0; p < 4; p++) {
#pragma unroll
        for (int h = 0; h < 2; h++) {
            int r = row0 + ty * 8 + p * 2 + h;
            if (r < N_NODES) {
                float s = g_dinv[r];
                float4 o;
                float2 c0 = *(float2*)&acc[p][0];
                float2 c1 = *(float2*)&acc[p][1];
                float2 c2 = *(float2*)&acc[p][2];
                float2 c3 = *(float2*)&acc[p][3];
                o.x = (h == 0 ? c0.x : c0.y) * s;
                o.y = (h == 0 ? c1.x : c1.y) * s;
                o.z = (h == 0 ? c2.x : c2.y) * s;
                o.w = (h == 0 ? c3.x : c3.y) * s;
                *(float4*)&U[(size_t)r * ncols + col0 + tx * 4] = o;
            }
        }
    }
}

// ---------------- aggregation: out[i] = act( dinv[i]*(sum_nbr u[src] + u[i]) + b ) ----------------
// One warp per destination node. VECS = row width in float4 (32 for D=128, 16 for D=64).
template <int VECS>
__global__ void k_agg(const float4* __restrict__ U, const float* __restrict__ bias,
                      float* __restrict__ out, int do_relu) {
    int gw = (blockIdx.x * blockDim.x + threadIdx.x) >> 5;
    int lane = threadIdx.x & 31;
    if (gw >= N_NODES) return;
    if (lane >= VECS) return;

    float4 acc = U[(size_t)gw * VECS + lane];  // self loop term u[i]
    int e0 = g_off[gw];
    int e1 = g_off[gw + 1];
    int e = e0;
    for (; e + 1 < e1; e += 2) {
        int s0 = g_col[e];
        int s1 = g_col[e + 1];
        float4 v0 = U[(size_t)s0 * VECS + lane];
        float4 v1 = U[(size_t)s1 * VECS + lane];
        acc.x += v0.x + v1.x;
        acc.y += v0.y + v1.y;
        acc.z += v0.z + v1.z;
        acc.w += v0.w + v1.w;
    }
    if (e < e1) {
        int s0 = g_col[e];
        float4 v0 = U[(size_t)s0 * VECS + lane];
        acc.x += v0.x; acc.y += v0.y; acc.z += v0.z; acc.w += v0.w;
    }

    float d = g_dinv[gw];
    float4 b4 = *(const float4*)&bias[lane * 4];
    float4 o;
    o.x = fmaf(acc.x, d, b4.x);
    o.y = fmaf(acc.y, d, b4.y);
    o.z = fmaf(acc.z, d, b4.z);
    o.w = fmaf(acc.w, d, b4.w);
    if (do_relu) {
        o.x = fmaxf(o.x, 0.f);
        o.y = fmaxf(o.y, 0.f);
        o.z = fmaxf(o.z, 0.f);
        o.w = fmaxf(o.w, 0.f);
    }
    ((float4*)out)[(size_t)gw * VECS + lane] = o;
}

// ---------------- launch ----------------
extern "C" void kernel_launch(void* const* d_in, const int* in_sizes, int n_in,
                              void* d_out, int out_size) {
    const float* x  = (const float*)d_in[0];
    const void*  ei = d_in[1];
    const float* W1 = (const float*)d_in[2];
    const float* b1 = (const float*)d_in[3];
    const float* W2 = (const float*)d_in[4];
    const float* b2 = (const float*)d_in[5];
    const float* W3 = (const float*)d_in[6];
    const float* b3 = (const float*)d_in[7];
    float* out = (float*)d_out;

    float *bufA, *bufB;
    cudaGetSymbolAddress((void**)&bufA, g_bufA);
    cudaGetSymbolAddress((void**)&bufB, g_bufB);

    const int TB = 256;
    // detect edge dtype, then graph prep: degree -> dinv -> CSR
    k_detect<<<1, 1>>>((const long long*)ei);
    k_zero<<<(N_NODES + TB - 1) / TB, TB>>>();
    k_count<<<(N_EDGES + TB - 1) / TB, TB>>>(ei);
    k_dinv<<<(N_NODES + TB - 1) / TB, TB>>>();
    k_scan<<<1, 1024>>>();
    k_scatter<<<(N_EDGES + TB - 1) / TB, TB>>>(ei);

    dim3 g2((N_NODES + 127) / 128, 2);
    dim3 g1((N_NODES + 127) / 128, 1);
    int agg_blocks = (N_NODES * 32 + TB - 1) / TB;

    // layer 1: u = dinv .* (x @ W1); h1 = relu(dinv*(agg u) + b1)
    k_gemm<<<g2, TB>>>(x, W1, bufA, 128);
    k_agg<32><<<agg_blocks, TB>>>((const float4*)bufA, b1, bufB, 1);
    // layer 2
    k_gemm<<<g2, TB>>>(bufB, W2, bufA, 128);
    k_agg<32><<<agg_blocks, TB>>>((const float4*)bufA, b2, bufB, 1);
    // layer 3 (no relu), D_out = 64
    k_gemm<<<g1, TB>>>(bufB, W3, bufA, 64);
    k_agg<16><<<agg_blocks, TB>>>((const float4*)bufA, b3, out, 0);
}

// round 3
// speedup vs baseline: 1.3628x; 1.3628x over previous
#include <cuda_runtime.h>
#include <cuda_fp16.h>
#include <cstddef>

#define N_NODES 50000
#define N_EDGES 800000
#define NBLK 196   // ceil(50000/256)

// ---------------- scratch (static device arrays; no allocation) ----------------
__device__ __align__(16) __half g_bufU[N_NODES * 128];  // gathered buffer (fp16)
__device__ __align__(16) float  g_bufH[N_NODES * 128];  // post-agg activations (fp32)
__device__ float g_dinv[N_NODES];
__device__ int   g_cnt[N_NODES];
__device__ int   g_off[N_NODES + 1];
__device__ int   g_cur[N_NODES];
__device__ int   g_col[N_EDGES];
__device__ int   g_part[NBLK];
__device__ int   g_partoff[NBLK];
__device__ int   g_is32;

// ---------------- packed f32x2 helpers (Blackwell) ----------------
__device__ __forceinline__ unsigned long long fma2(unsigned long long a,
                                                   unsigned long long b,
                                                   unsigned long long c) {
    unsigned long long d;
    asm("fma.rn.f32x2 %0, %1, %2, %3;" : "=l"(d) : "l"(a), "l"(b), "l"(c));
    return d;
}
__device__ __forceinline__ unsigned long long pack2(float x, float y) {
    unsigned long long d;
    asm("mov.b64 %0, {%1, %2};" : "=l"(d) : "f"(x), "f"(y));
    return d;
}

// edge accessor: handles int32 vs int64 storage (flag set by k_detect)
__device__ __forceinline__ int edge_at(const void* ei, size_t idx) {
    if (g_is32) return ((const int*)ei)[idx];
    return (int)((const long long*)ei)[idx];
}

// ---------------- dtype detection ----------------
__global__ void k_detect(const long long* __restrict__ ei64) {
    int is32 = 0;
    for (int i = 0; i < 64; i++) {
        long long v = ei64[i];
        if (v < 0 || v >= N_NODES) { is32 = 1; break; }
    }
    g_is32 = is32;
}

// ---------------- graph prep ----------------
__global__ void k_count(const void* __restrict__ ei) {
    int e = blockIdx.x * blockDim.x + threadIdx.x;
    if (e < N_EDGES) {
        int dst = edge_at(ei, (size_t)N_EDGES + e);
        atomicAdd(&g_cnt[dst], 1);
    }
}

// phase 1: per-block sum of counts (+ fused dinv)
__global__ void k_s1() {
    __shared__ int sm[256];
    int tid = threadIdx.x;
    int i = blockIdx.x * 256 + tid;
    int v = (i < N_NODES) ? g_cnt[i] : 0;
    if (i < N_NODES) g_dinv[i] = rsqrtf((float)v + 1.0f);  // +1 = self loop
    sm[tid] = v;
    __syncthreads();
#pragma unroll
    for (int s = 128; s > 0; s >>= 1) {
        if (tid < s) sm[tid] += sm[tid + s];
        __syncthreads();
    }
    if (tid == 0) g_part[blockIdx.x] = sm[0];
}

// phase 2: single-block exclusive scan of NBLK partials
__global__ void k_s2() {
    __shared__ int sm[256];
    int tid = threadIdx.x;
    int v = (tid < NBLK) ? g_part[tid] : 0;
    sm[tid] = v;
    __syncthreads();
#pragma unroll
    for (int s = 1; s < 256; s <<= 1) {
        int t = (tid >= s) ? sm[tid - s] : 0;
        __syncthreads();
        sm[tid] += t;
        __syncthreads();
    }
    if (tid < NBLK) g_partoff[tid] = sm[tid] - v;  // exclusive
}

// phase 3: per-block exclusive scan + block offset -> g_off / g_cur
__global__ void k_s3() {
    __shared__ int sm[256];
    int tid = threadIdx.x;
    int i = blockIdx.x * 256 + tid;
    int v = (i < N_NODES) ? g_cnt[i] : 0;
    sm[tid] = v;
    __syncthreads();
#pragma unroll
    for (int s = 1; s < 256; s <<= 1) {
        int t = (tid >= s) ? sm[tid - s] : 0;
        __syncthreads();
        sm[tid] += t;
        __syncthreads();
    }
    if (i < N_NODES) {
        int o = g_partoff[blockIdx.x] + sm[tid] - v;
        g_off[i] = o;
        g_cur[i] = o;
    }
    if (blockIdx.x == 0 && tid == 0) g_off[N_NODES] = N_EDGES;
}

__global__ void k_scatter(const void* __restrict__ ei) {
    int e = blockIdx.x * blockDim.x + threadIdx.x;
    if (e < N_EDGES) {
        int src = edge_at(ei, (size_t)e);
        int dst = edge_at(ei, (size_t)N_EDGES + e);
        int pos = atomicAdd(&g_cur[dst], 1);
        g_col[pos] = src;
    }
}

// ---------------- GEMM: U = fp16( dinv .* (A @ W) ) ----------------
// A: [N_NODES, 128] fp32 row-major. W: [128, ncols]. U: [N_NODES, ncols] fp16.
// Tile BM=128, BN=64, BK=32. 256 threads, 8 rows x 4 cols each, f32x2 FMA.
__global__ void k_gemm(const float* __restrict__ A, const float* __restrict__ W,
                       __half* __restrict__ U, int ncols) {
    __shared__ __align__(16) float As[32 * 128];  // transposed: As[k*128 + m]
    __shared__ __align__(16) float Ws[32 * 64];   // Ws[k*64 + n]
    int tid = threadIdx.x;
    int tx = tid & 15;   // 0..15 -> 4 cols each
    int ty = tid >> 4;   // 0..15 -> 8 rows each
    int row0 = blockIdx.x * 128;
    int col0 = blockIdx.y * 64;

    unsigned long long acc[4][4];
#pragma unroll
    for (int p = 0; p < 4; p++)
#pragma unroll
        for (int j = 0; j < 4; j++) acc[p][j] = 0ULL;

    for (int kt = 0; kt < 128; kt += 32) {
#pragma unroll
        for (int j = 0; j < 4; j++) {
            int f = tid + 256 * j;
            int r = f >> 3;
            int kc = (f & 7) << 2;
            int row = row0 + r;
            float4 v = make_float4(0.f, 0.f, 0.f, 0.f);
            if (row < N_NODES)
                v = *(const float4*)&A[(size_t)row * 128 + kt + kc];
            As[(kc + 0) * 128 + r] = v.x;
            As[(kc + 1) * 128 + r] = v.y;
            As[(kc + 2) * 128 + r] = v.z;
            As[(kc + 3) * 128 + r] = v.w;
        }
#pragma unroll
        for (int j = 0; j < 2; j++) {
            int f = tid + 256 * j;
            int kr = f >> 4;
            int cc = (f & 15) << 2;
            *(float4*)&Ws[kr * 64 + cc] =
                *(const float4*)&W[(size_t)(kt + kr) * ncols + col0 + cc];
        }
        __syncthreads();

#pragma unroll
        for (int k = 0; k < 32; k++) {
            ulonglong2 a01 = *(const ulonglong2*)&As[k * 128 + ty * 8];
            ulonglong2 a23 = *(const ulonglong2*)&As[k * 128 + ty * 8 + 4];
            float4 bv = *(const float4*)&Ws[k * 64 + tx * 4];
            unsigned long long av[4] = {a01.x, a01.y, a23.x, a23.y};
            unsigned long long bb[4] = {pack2(bv.x, bv.x), pack2(bv.y, bv.y),
                                        pack2(bv.z, bv.z), pack2(bv.w, bv.w)};
#pragma unroll
            for (int p = 0; p < 4; p++)
#pragma unroll
                for (int j = 0; j < 4; j++)
                    acc[p][j] = fma2(av[p], bb[j], acc[p][j]);
        }
        __syncthreads();
    }

    // epilogue: scale by dinv[row], convert to fp16, write U
#pragma unroll
    for (int p = 0; p < 4; p++) {
        float2 c0 = *(float2*)&acc[p][0];
        float2 c1 = *(float2*)&acc[p][1];
        float2 c2 = *(float2*)&acc[p][2];
        float2 c3 = *(float2*)&acc[p][3];
#pragma unroll
        for (int h = 0; h < 2; h++) {
            int r = row0 + ty * 8 + p * 2 + h;
            if (r < N_NODES) {
                float s = g_dinv[r];
                float ox = (h == 0 ? c0.x : c0.y) * s;
                float oy = (h == 0 ? c1.x : c1.y) * s;
                float oz = (h == 0 ? c2.x : c2.y) * s;
                float ow = (h == 0 ? c3.x : c3.y) * s;
                __half2 p01 = __floats2half2_rn(ox, oy);
                __half2 p23 = __floats2half2_rn(oz, ow);
                uint2 st;
                st.x = *(unsigned*)&p01;
                st.y = *(unsigned*)&p23;
                *(uint2*)&U[(size_t)r * ncols + col0 + tx * 4] = st;
            }
        }
    }
}

// ---------------- aggregation (D=128): out[i] = act( dinv[i]*(sum u[src] + u[i]) + b ) ----------------
// One warp per node; each lane handles 4 features (8B fp16 per gather row slice).
__global__ void k_agg128(const __half* __restrict__ U, const float* __restrict__ bias,
                         float* __restrict__ out, int do_relu) {
    int gw = (blockIdx.x * blockDim.x + threadIdx.x) >> 5;
    int lane = threadIdx.x & 31;
    if (gw >= N_NODES) return;
    const uint2* U2 = (const uint2*)U;

    uint2 raw = U2[(size_t)gw * 32 + lane];  // self term
    float2 f0 = __half22float2(*(__half2*)&raw.x);
    float2 f1 = __half22float2(*(__half2*)&raw.y);
    float ax = f0.x, ay = f0.y, az = f1.x, aw = f1.y;

    int e = g_off[gw];
    int e1 = g_off[gw + 1];
    for (; e + 3 < e1; e += 4) {
        int s0 = g_col[e], s1 = g_col[e + 1], s2 = g_col[e + 2], s3 = g_col[e + 3];
        uint2 r0 = U2[(size_t)s0 * 32 + lane];
        uint2 r1 = U2[(size_t)s1 * 32 + lane];
        uint2 r2 = U2[(size_t)s2 * 32 + lane];
        uint2 r3 = U2[(size_t)s3 * 32 + lane];
        float2 a0 = __half22float2(*(__half2*)&r0.x), b0 = __half22float2(*(__half2*)&r0.y);
        float2 a1 = __half22float2(*(__half2*)&r1.x), b1 = __half22float2(*(__half2*)&r1.y);
        float2 a2 = __half22float2(*(__half2*)&r2.x), b2 = __half22float2(*(__half2*)&r2.y);
        float2 a3 = __half22float2(*(__half2*)&r3.x), b3 = __half22float2(*(__half2*)&r3.y);
        ax += (a0.x + a1.x) + (a2.x + a3.x);
        ay += (a0.y + a1.y) + (a2.y + a3.y);
        az += (b0.x + b1.x) + (b2.x + b3.x);
        aw += (b0.y + b1.y) + (b2.y + b3.y);
    }
    for (; e < e1; e++) {
        int s0 = g_col[e];
        uint2 r0 = U2[(size_t)s0 * 32 + lane];
        float2 a0 = __half22float2(*(__half2*)&r0.x), b0 = __half22float2(*(__half2*)&r0.y);
        ax += a0.x; ay += a0.y; az += b0.x; aw += b0.y;
    }

    float d = g_dinv[gw];
    float4 b4 = *(const float4*)&bias[lane * 4];
    float4 o;
    o.x = fmaf(ax, d, b4.x);
    o.y = fmaf(ay, d, b4.y);
    o.z = fmaf(az, d, b4.z);
    o.w = fmaf(aw, d, b4.w);
    if (do_relu) {
        o.x = fmaxf(o.x, 0.f); o.y = fmaxf(o.y, 0.f);
        o.z = fmaxf(o.z, 0.f); o.w = fmaxf(o.w, 0.f);
    }
    ((float4*)out)[(size_t)gw * 32 + lane] = o;
}

// ---------------- aggregation (D=64): final layer, no relu ----------------
__global__ void k_agg64(const __half* __restrict__ U, const float* __restrict__ bias,
                        float* __restrict__ out) {
    int gw = (blockIdx.x * blockDim.x + threadIdx.x) >> 5;
    int lane = threadIdx.x & 31;
    if (gw >= N_NODES) return;
    const unsigned* U1 = (const unsigned*)U;

    unsigned raw = U1[(size_t)gw * 32 + lane];
    float2 acc = __half22float2(*(__half2*)&raw);

    int e = g_off[gw];
    int e1 = g_off[gw + 1];
    for (; e + 3 < e1; e += 4) {
        int s0 = g_col[e], s1 = g_col[e + 1], s2 = g_col[e + 2], s3 = g_col[e + 3];
        unsigned r0 = U1[(size_t)s0 * 32 + lane];
        unsigned r1 = U1[(size_t)s1 * 32 + lane];
        unsigned r2 = U1[(size_t)s2 * 32 + lane];
        unsigned r3 = U1[(size_t)s3 * 32 + lane];
        float2 a0 = __half22float2(*(__half2*)&r0);
        float2 a1 = __half22float2(*(__half2*)&r1);
        float2 a2 = __half22float2(*(__half2*)&r2);
        float2 a3 = __half22float2(*(__half2*)&r3);
        acc.x += (a0.x + a1.x) + (a2.x + a3.x);
        acc.y += (a0.y + a1.y) + (a2.y + a3.y);
    }
    for (; e < e1; e++) {
        unsigned r0 = U1[(size_t)g_col[e] * 32 + lane];
        float2 a0 = __half22float2(*(__half2*)&r0);
        acc.x += a0.x; acc.y += a0.y;
    }

    float d = g_dinv[gw];
    float2 b2 = *(const float2*)&bias[lane * 2];
    float2 o;
    o.x = fmaf(acc.x, d, b2.x);
    o.y = fmaf(acc.y, d, b2.y);
    ((float2*)out)[(size_t)gw * 32 + lane] = o;
}

// ---------------- launch ----------------
extern "C" void kernel_launch(void* const* d_in, const int* in_sizes, int n_in,
                              void* d_out, int out_size) {
    const float* x  = (const float*)d_in[0];
    const void*  ei = d_in[1];
    const float* W1 = (const float*)d_in[2];
    const float* b1 = (const float*)d_in[3];
    const float* W2 = (const float*)d_in[4];
    const float* b2 = (const float*)d_in[5];
    const float* W3 = (const float*)d_in[6];
    const float* b3 = (const float*)d_in[7];
    float* out = (float*)d_out;

    __half* bufU; float* bufH; int* cnt;
    cudaGetSymbolAddress((void**)&bufU, g_bufU);
    cudaGetSymbolAddress((void**)&bufH, g_bufH);
    cudaGetSymbolAddress((void**)&cnt, g_cnt);

    const int TB = 256;
    // edge dtype detect + graph prep: degree -> dinv -> CSR (parallel scan)
    k_detect<<<1, 1>>>((const long long*)ei);
    cudaMemsetAsync(cnt, 0, N_NODES * sizeof(int));
    k_count<<<(N_EDGES + TB - 1) / TB, TB>>>(ei);
    k_s1<<<NBLK, TB>>>();
    k_s2<<<1, 256>>>();
    k_s3<<<NBLK, TB>>>();
    k_scatter<<<(N_EDGES + TB - 1) / TB, TB>>>(ei);

    dim3 g2((N_NODES + 127) / 128, 2);
    dim3 g1((N_NODES + 127) / 128, 1);
    int agg_blocks = (N_NODES * 32 + TB - 1) / TB;

    // layer 1: U = fp16(dinv .* (x @ W1)); h1 = relu(dinv*(agg U) + b1)
    k_gemm<<<g2, TB>>>(x, W1, bufU, 128);
    k_agg128<<<agg_blocks, TB>>>(bufU, b1, bufH, 1);
    // layer 2
    k_gemm<<<g2, TB>>>(bufH, W2, bufU, 128);
    k_agg128<<<agg_blocks, TB>>>(bufU, b2, bufH, 1);
    // layer 3 (no relu), D_out = 64
    k_gemm<<<g1, TB>>>(bufH, W3, bufU, 64);
    k_agg64<<<agg_blocks, TB>>>(bufU, b3, out);
}

// round 4
// speedup vs baseline: 2.1571x; 1.5828x over previous
#include <cuda_runtime.h>
#include <cuda_fp16.h>
#include <mma.h>
#include <cstddef>

using namespace nvcuda;

#define N_NODES 50000
#define N_EDGES 800000
#define NBLK 196   // ceil(50000/256)

// ---------------- scratch (static device arrays; no allocation) ----------------
__device__ __align__(16) __half g_bufU[N_NODES * 128];  // GEMM output (gathered)
__device__ __align__(16) __half g_bufH[N_NODES * 128];  // activations (GEMM input)
__device__ __align__(16) __half g_Wh[40960];            // W1(16384) W2(16384) W3(8192) fp16
__device__ float g_dinv[N_NODES];
__device__ int   g_cnt[N_NODES];
__device__ int   g_off[N_NODES + 1];
__device__ int   g_cur[N_NODES];
__device__ int   g_col[N_EDGES];
__device__ int   g_part[NBLK];
__device__ int   g_partoff[NBLK];
__device__ int   g_is32;

// edge accessor: handles int32 vs int64 storage (flag set by k_detect)
__device__ __forceinline__ int edge_at(const void* ei, size_t idx) {
    if (g_is32) return ((const int*)ei)[idx];
    return (int)((const long long*)ei)[idx];
}

// ---------------- dtype detection (parallel) ----------------
// If stored int32, an int64-interpreted word packs two values in [0,50000):
// high half nonzero w.h.p. => out of range. 64 words checked in parallel.
__global__ void k_detect(const long long* __restrict__ ei64) {
    __shared__ int flag;
    if (threadIdx.x == 0) flag = 0;
    __syncthreads();
    long long v = ei64[threadIdx.x];
    if (v < 0 || v >= N_NODES) flag = 1;
    __syncthreads();
    if (threadIdx.x == 0) g_is32 = flag;
}

// ---------------- graph prep ----------------
__global__ void k_count(const void* __restrict__ ei) {
    int e = blockIdx.x * blockDim.x + threadIdx.x;
    if (e < N_EDGES) {
        int dst = edge_at(ei, (size_t)N_EDGES + e);
        atomicAdd(&g_cnt[dst], 1);
    }
}

// phase 1: per-block sum of counts (+ fused dinv)
__global__ void k_s1() {
    __shared__ int sm[256];
    int tid = threadIdx.x;
    int i = blockIdx.x * 256 + tid;
    int v = (i < N_NODES) ? g_cnt[i] : 0;
    if (i < N_NODES) g_dinv[i] = rsqrtf((float)v + 1.0f);  // +1 = self loop
    sm[tid] = v;
    __syncthreads();
#pragma unroll
    for (int s = 128; s > 0; s >>= 1) {
        if (tid < s) sm[tid] += sm[tid + s];
        __syncthreads();
    }
    if (tid == 0) g_part[blockIdx.x] = sm[0];
}

// phase 2: single-block exclusive scan of NBLK partials (shuffle-based)
__global__ void k_s2() {
    int tid = threadIdx.x;
    int lane = tid & 31, w = tid >> 5;
    int v = (tid < NBLK) ? g_part[tid] : 0;
    int s = v;
#pragma unroll
    for (int o = 1; o < 32; o <<= 1) {
        int t = __shfl_up_sync(0xffffffffu, s, o);
        if (lane >= o) s += t;
    }
    __shared__ int ws[8];
    if (lane == 31) ws[w] = s;
    __syncthreads();
    if (tid == 0) {
        int run = 0;
#pragma unroll
        for (int i = 0; i < 8; i++) { int t = ws[i]; ws[i] = run; run += t; }
    }
    __syncthreads();
    if (tid < NBLK) g_partoff[tid] = ws[w] + s - v;  // exclusive
}

// phase 3: per-block exclusive scan + block offset -> g_off / g_cur
__global__ void k_s3() {
    __shared__ int sm[256];
    int tid = threadIdx.x;
    int i = blockIdx.x * 256 + tid;
    int v = (i < N_NODES) ? g_cnt[i] : 0;
    sm[tid] = v;
    __syncthreads();
#pragma unroll
    for (int s = 1; s < 256; s <<= 1) {
        int t = (tid >= s) ? sm[tid - s] : 0;
        __syncthreads();
        sm[tid] += t;
        __syncthreads();
    }
    if (i < N_NODES) {
        int o = g_partoff[blockIdx.x] + sm[tid] - v;
        g_off[i] = o;
        g_cur[i] = o;
    }
    if (blockIdx.x == 0 && tid == 0) g_off[N_NODES] = N_EDGES;
}

__global__ void k_scatter(const void* __restrict__ ei) {
    int e = blockIdx.x * blockDim.x + threadIdx.x;
    if (e < N_EDGES) {
        int src = edge_at(ei, (size_t)e);
        int dst = edge_at(ei, (size_t)N_EDGES + e);
        int pos = atomicAdd(&g_cur[dst], 1);
        g_col[pos] = src;
    }
}

// ---------------- fp32 -> fp16 conversion ----------------
__global__ void k_cvtX(const float* __restrict__ x, __half* __restrict__ xh) {
    int i = blockIdx.x * blockDim.x + threadIdx.x;   // float4 index
    if (i < N_NODES * 32) {
        float4 v = ((const float4*)x)[i];
        __half2 a = __floats2half2_rn(v.x, v.y);
        __half2 b = __floats2half2_rn(v.z, v.w);
        uint2 st; st.x = *(unsigned*)&a; st.y = *(unsigned*)&b;
        ((uint2*)xh)[i] = st;
    }
}

__global__ void k_cvtW(const float* __restrict__ W1, const float* __restrict__ W2,
                       const float* __restrict__ W3) {
    int i = blockIdx.x * blockDim.x + threadIdx.x;
    if (i < 40960) {
        float v;
        if (i < 16384) v = W1[i];
        else if (i < 32768) v = W2[i - 16384];
        else v = W3[i - 32768];
        g_Wh[i] = __float2half_rn(v);
    }
}

// ---------------- GEMM (tensor cores): U = fp16( dinv .* (A @ W) ) ----------------
// A: [N_NODES, 128] fp16 row-major. W: [128, NCOLS] fp16. U: [N_NODES, NCOLS] fp16.
// Block: 256 threads (8 warps), M-tile 128 (16 rows/warp), full N in block.
template <int NCOLS>
__global__ void k_wgemm(const __half* __restrict__ A, const __half* __restrict__ Wh,
                        __half* __restrict__ U) {
    extern __shared__ __align__(16) char smem_raw[];
    const int LDA = 136;          // 128 + 8 halves padding
    const int LDB = NCOLS + 8;
    __half* As = (__half*)smem_raw;              // 128 x LDA
    __half* Ws = (__half*)smem_raw + 128 * LDA;  // 128 x LDB
    float* stage = (float*)smem_raw;             // reused after mainloop

    int tid = threadIdx.x;
    int warp = tid >> 5, lane = tid & 31;
    int row0 = blockIdx.x * 128;

    // load A tile (128 x 128 halves), uint4 = 8 halves
    for (int i = tid; i < 128 * 16; i += 256) {
        int r = i >> 4, c8 = i & 15;
        int row = row0 + r;
        uint4 v = make_uint4(0u, 0u, 0u, 0u);
        if (row < N_NODES) v = *(const uint4*)&A[(size_t)row * 128 + c8 * 8];
        *(uint4*)&As[r * LDA + c8 * 8] = v;
    }
    // load W tile (128 x NCOLS)
    for (int i = tid; i < 128 * (NCOLS / 8); i += 256) {
        int r = i / (NCOLS / 8), c8 = i % (NCOLS / 8);
        *(uint4*)&Ws[r * LDB + c8 * 8] = *(const uint4*)&Wh[(size_t)r * NCOLS + c8 * 8];
    }
    __syncthreads();

    const int NF = NCOLS / 16;
    wmma::fragment<wmma::accumulator, 16, 16, 16, float> acc[NF];
#pragma unroll
    for (int n = 0; n < NF; n++) wmma::fill_fragment(acc[n], 0.0f);

#pragma unroll
    for (int k = 0; k < 8; k++) {
        wmma::fragment<wmma::matrix_a, 16, 16, 16, __half, wmma::row_major> a;
        wmma::load_matrix_sync(a, &As[(warp * 16) * LDA + k * 16], LDA);
#pragma unroll
        for (int n = 0; n < NF; n++) {
            wmma::fragment<wmma::matrix_b, 16, 16, 16, __half, wmma::row_major> b;
            wmma::load_matrix_sync(b, &Ws[(k * 16) * LDB + n * 16], LDB);
            wmma::mma_sync(acc[n], a, b, acc[n]);
        }
    }
    __syncthreads();  // done with As/Ws; reuse as stage

    // epilogue: stage fp32 frag, scale by dinv[row], pack fp16, 16B stores
    float* wst = stage + warp * (16 * 20);
    int r = lane >> 1, c0 = (lane & 1) * 8;
    int row = row0 + warp * 16 + r;
    float d = (row < N_NODES) ? g_dinv[row] : 0.0f;
#pragma unroll
    for (int n = 0; n < NF; n++) {
        wmma::store_matrix_sync(wst, acc[n], 20, wmma::mem_row_major);
        __syncwarp();
        if (row < N_NODES) {
            const float* src = wst + r * 20 + c0;
            __half2 h0 = __floats2half2_rn(src[0] * d, src[1] * d);
            __half2 h1 = __floats2half2_rn(src[2] * d, src[3] * d);
            __half2 h2 = __floats2half2_rn(src[4] * d, src[5] * d);
            __half2 h3 = __floats2half2_rn(src[6] * d, src[7] * d);
            uint4 st;
            st.x = *(unsigned*)&h0; st.y = *(unsigned*)&h1;
            st.z = *(unsigned*)&h2; st.w = *(unsigned*)&h3;
            *(uint4*)&U[(size_t)row * NCOLS + n * 16 + c0] = st;
        }
        __syncwarp();
    }
}

// ---------------- aggregation (D=128): h[i] = fp16( relu( dinv[i]*(sum u[src] + u[i]) + b ) ) ----------------
__global__ void k_agg128(const __half* __restrict__ U, const float* __restrict__ bias,
                         __half* __restrict__ out) {
    int gw = (blockIdx.x * blockDim.x + threadIdx.x) >> 5;
    int lane = threadIdx.x & 31;
    if (gw >= N_NODES) return;
    const uint2* U2 = (const uint2*)U;

    uint2 raw = U2[(size_t)gw * 32 + lane];  // self term
    float2 f0 = __half22float2(*(__half2*)&raw.x);
    float2 f1 = __half22float2(*(__half2*)&raw.y);
    float ax = f0.x, ay = f0.y, az = f1.x, aw = f1.y;

    int e = g_off[gw];
    int e1 = g_off[gw + 1];
    for (; e + 3 < e1; e += 4) {
        int s0 = g_col[e], s1 = g_col[e + 1], s2 = g_col[e + 2], s3 = g_col[e + 3];
        uint2 r0 = U2[(size_t)s0 * 32 + lane];
        uint2 r1 = U2[(size_t)s1 * 32 + lane];
        uint2 r2 = U2[(size_t)s2 * 32 + lane];
        uint2 r3 = U2[(size_t)s3 * 32 + lane];
        float2 a0 = __half22float2(*(__half2*)&r0.x), b0 = __half22float2(*(__half2*)&r0.y);
        float2 a1 = __half22float2(*(__half2*)&r1.x), b1 = __half22float2(*(__half2*)&r1.y);
        float2 a2 = __half22float2(*(__half2*)&r2.x), b2 = __half22float2(*(__half2*)&r2.y);
        float2 a3 = __half22float2(*(__half2*)&r3.x), b3 = __half22float2(*(__half2*)&r3.y);
        ax += (a0.x + a1.x) + (a2.x + a3.x);
        ay += (a0.y + a1.y) + (a2.y + a3.y);
        az += (b0.x + b1.x) + (b2.x + b3.x);
        aw += (b0.y + b1.y) + (b2.y + b3.y);
    }
    for (; e < e1; e++) {
        int s0 = g_col[e];
        uint2 r0 = U2[(size_t)s0 * 32 + lane];
        float2 a0 = __half22float2(*(__half2*)&r0.x), b0 = __half22float2(*(__half2*)&r0.y);
        ax += a0.x; ay += a0.y; az += b0.x; aw += b0.y;
    }

    float d = g_dinv[gw];
    float4 b4 = *(const float4*)&bias[lane * 4];
    float ox = fmaxf(fmaf(ax, d, b4.x), 0.f);
    float oy = fmaxf(fmaf(ay, d, b4.y), 0.f);
    float oz = fmaxf(fmaf(az, d, b4.z), 0.f);
    float ow = fmaxf(fmaf(aw, d, b4.w), 0.f);
    __half2 p01 = __floats2half2_rn(ox, oy);
    __half2 p23 = __floats2half2_rn(oz, ow);
    uint2 st; st.x = *(unsigned*)&p01; st.y = *(unsigned*)&p23;
    ((uint2*)out)[(size_t)gw * 32 + lane] = st;
}

// ---------------- aggregation (D=64): final layer, fp32 out, no relu ----------------
__global__ void k_agg64(const __half* __restrict__ U, const float* __restrict__ bias,
                        float* __restrict__ out) {
    int gw = (blockIdx.x * blockDim.x + threadIdx.x) >> 5;
    int lane = threadIdx.x & 31;
    if (gw >= N_NODES) return;
    const unsigned* U1 = (const unsigned*)U;

    unsigned raw = U1[(size_t)gw * 32 + lane];
    float2 acc = __half22float2(*(__half2*)&raw);

    int e = g_off[gw];
    int e1 = g_off[gw + 1];
    for (; e + 3 < e1; e += 4) {
        int s0 = g_col[e], s1 = g_col[e + 1], s2 = g_col[e + 2], s3 = g_col[e + 3];
        unsigned r0 = U1[(size_t)s0 * 32 + lane];
        unsigned r1 = U1[(size_t)s1 * 32 + lane];
        unsigned r2 = U1[(size_t)s2 * 32 + lane];
        unsigned r3 = U1[(size_t)s3 * 32 + lane];
        float2 a0 = __half22float2(*(__half2*)&r0);
        float2 a1 = __half22float2(*(__half2*)&r1);
        float2 a2 = __half22float2(*(__half2*)&r2);
        float2 a3 = __half22float2(*(__half2*)&r3);
        acc.x += (a0.x + a1.x) + (a2.x + a3.x);
        acc.y += (a0.y + a1.y) + (a2.y + a3.y);
    }
    for (; e < e1; e++) {
        unsigned r0 = U1[(size_t)g_col[e] * 32 + lane];
        float2 a0 = __half22float2(*(__half2*)&r0);
        acc.x += a0.x; acc.y += a0.y;
    }

    float d = g_dinv[gw];
    float2 b2 = *(const float2*)&bias[lane * 2];
    float2 o;
    o.x = fmaf(acc.x, d, b2.x);
    o.y = fmaf(acc.y, d, b2.y);
    ((float2*)out)[(size_t)gw * 32 + lane] = o;
}

// ---------------- launch ----------------
extern "C" void kernel_launch(void* const* d_in, const int* in_sizes, int n_in,
                              void* d_out, int out_size) {
    const float* x  = (const float*)d_in[0];
    const void*  ei = d_in[1];
    const float* W1 = (const float*)d_in[2];
    const float* b1 = (const float*)d_in[3];
    const float* W2 = (const float*)d_in[4];
    const float* b2 = (const float*)d_in[5];
    const float* W3 = (const float*)d_in[6];
    const float* b3 = (const float*)d_in[7];
    float* out = (float*)d_out;

    __half *bufU, *bufH, *Wh;
    int* cnt;
    cudaGetSymbolAddress((void**)&bufU, g_bufU);
    cudaGetSymbolAddress((void**)&bufH, g_bufH);
    cudaGetSymbolAddress((void**)&Wh, g_Wh);
    cudaGetSymbolAddress((void**)&cnt, g_cnt);

    const int TB = 256;
    const int SMEM128 = (128 * 136 + 128 * 136) * 2;  // 69632
    const int SMEM64  = (128 * 136 + 128 * 72) * 2;   // 53248
    cudaFuncSetAttribute(k_wgemm<128>, cudaFuncAttributeMaxDynamicSharedMemorySize, SMEM128);
    cudaFuncSetAttribute(k_wgemm<64>,  cudaFuncAttributeMaxDynamicSharedMemorySize, SMEM64);

    // edge dtype detect + graph prep: degree -> dinv -> CSR (parallel scan)
    k_detect<<<1, 64>>>((const long long*)ei);
    cudaMemsetAsync(cnt, 0, N_NODES * sizeof(int));
    k_count<<<(N_EDGES + TB - 1) / TB, TB>>>(ei);
    k_s1<<<NBLK, TB>>>();
    k_s2<<<1, 256>>>();
    k_s3<<<NBLK, TB>>>();
    k_scatter<<<(N_EDGES + TB - 1) / TB, TB>>>(ei);

    // conversions to fp16
    k_cvtX<<<(N_NODES * 32 + TB - 1) / TB, TB>>>(x, bufH);
    k_cvtW<<<(40960 + TB - 1) / TB, TB>>>(W1, W2, W3);

    int gemm_blocks = (N_NODES + 127) / 128;
    int agg_blocks = (N_NODES * 32 + TB - 1) / TB;

    // layer 1
    k_wgemm<128><<<gemm_blocks, TB, SMEM128>>>(bufH, Wh, bufU);
    k_agg128<<<agg_blocks, TB>>>(bufU, b1, bufH);
    // layer 2
    k_wgemm<128><<<gemm_blocks, TB, SMEM128>>>(bufH, Wh + 16384, bufU);
    k_agg128<<<agg_blocks, TB>>>(bufU, b2, bufH);
    // layer 3 (no relu), D_out = 64
    k_wgemm<64><<<gemm_blocks, TB, SMEM64>>>(bufH, Wh + 32768, bufU);
    k_agg64<<<agg_blocks, TB>>>(bufU, b3, out);
}

// round 5
// speedup vs baseline: 2.2631x; 1.0492x over previous
#include <cuda_runtime.h>
#include <cuda_fp16.h>
#include <mma.h>
#include <cstddef>

using namespace nvcuda;

#define N_NODES 50000
#define N_EDGES 800000
#define NBLK 196   // ceil(50000/256)

// ---------------- scratch (static device arrays; no allocation) ----------------
__device__ __align__(16) __half g_bufU[N_NODES * 128];  // GEMM output (gathered)
__device__ __align__(16) __half g_bufH[N_NODES * 128];  // activations (GEMM input)
__device__ __align__(16) __half g_Wh[40960];            // W1(16384) W2(16384) W3(8192) fp16
__device__ float g_dinv[N_NODES];
// contiguous zero region: [0, N_NODES) = counts, [N_NODES, N_NODES+NBLK) = scan state
__device__ unsigned g_zero[N_NODES + NBLK];
__device__ int   g_off[N_NODES + 1];
__device__ int   g_cur[N_NODES];
__device__ int   g_col[N_EDGES];
__device__ int   g_is32;

#define g_cnt   ((int*)g_zero)
#define g_state (g_zero + N_NODES)

// edge accessor: handles int32 vs int64 storage (flag set by k_detect_cvtW)
__device__ __forceinline__ int edge_at(const void* ei, size_t idx) {
    if (g_is32) return ((const int*)ei)[idx];
    return (int)((const long long*)ei)[idx];
}

// ---------------- fused: dtype detection (block 0) + W fp32->fp16 (blocks 1..160) ----------------
// int32 storage => an int64-interpreted word packs two values in [0,50000):
// high half nonzero w.h.p. => out of range.
__global__ void k_detect_cvtW(const long long* __restrict__ ei64,
                              const float* __restrict__ W1,
                              const float* __restrict__ W2,
                              const float* __restrict__ W3) {
    if (blockIdx.x == 0) {
        __shared__ int flag;
        if (threadIdx.x == 0) flag = 0;
        __syncthreads();
        if (threadIdx.x < 64) {
            long long v = ei64[threadIdx.x];
            if (v < 0 || v >= N_NODES) flag = 1;
        }
        __syncthreads();
        if (threadIdx.x == 0) g_is32 = flag;
    } else {
        int i = (blockIdx.x - 1) * 256 + threadIdx.x;
        if (i < 40960) {
            float v;
            if (i < 16384) v = W1[i];
            else if (i < 32768) v = W2[i - 16384];
            else v = W3[i - 32768];
            g_Wh[i] = __float2half_rn(v);
        }
    }
}

// ---------------- graph prep ----------------
__global__ void k_count(const void* __restrict__ ei) {
    int e = blockIdx.x * blockDim.x + threadIdx.x;
    if (e < N_EDGES) {
        int dst = edge_at(ei, (size_t)N_EDGES + e);
        atomicAdd(&g_cnt[dst], 1);
    }
}

// single-pass decoupled-lookback exclusive scan of g_cnt -> g_off/g_cur (+ fused dinv)
// state word: status(2b)<<30 | value(30b). status: 0 invalid, 1 aggregate, 2 prefix.
__global__ void k_scan() {
    __shared__ int wsum[8];
    __shared__ int s_excl;
    int tid = threadIdx.x;
    int lane = tid & 31, w = tid >> 5;
    int b = blockIdx.x;
    int i = b * 256 + tid;

    int v = (i < N_NODES) ? g_cnt[i] : 0;
    if (i < N_NODES) g_dinv[i] = rsqrtf((float)v + 1.0f);  // +1 = self loop

    // warp inclusive scan
    int s = v;
#pragma unroll
    for (int o = 1; o < 32; o <<= 1) {
        int t = __shfl_up_sync(0xffffffffu, s, o);
        if (lane >= o) s += t;
    }
    if (lane == 31) wsum[w] = s;
    __syncthreads();
    if (tid == 0) {
        int run = 0;
#pragma unroll
        for (int k = 0; k < 8; k++) { int t = wsum[k]; wsum[k] = run; run += t; }
        // run == block total; publish aggregate (block 0 publishes prefix directly)
        __threadfence();
        unsigned st = (b == 0 ? 2u : 1u) << 30 | (unsigned)run;
        atomicExch(&g_state[b], st);
        wsum[0] = wsum[0];  // keep
    }
    __syncthreads();
    int block_total_dummy;
    (void)block_total_dummy;

    // warp 0: lookback for exclusive block prefix
    if (w == 0) {
        int running = 0;
        if (b > 0) {
            int j = b - 1;
            while (true) {
                int idx = j - lane;
                unsigned sv;
                if (idx >= 0) {
                    sv = atomicAdd(&g_state[idx], 0u);  // strong read
                } else {
                    sv = 2u << 30;  // virtual prefix 0
                }
                unsigned stt = sv >> 30;
                unsigned ball = __ballot_sync(0xffffffffu, stt >= 1u);
                if (ball != 0xffffffffu) continue;  // some invalid -> retry window
                unsigned pball = __ballot_sync(0xffffffffu, stt == 2u);
                if (pball) {
                    int fp = __ffs(pball) - 1;  // nearest prefix (smallest offset)
                    int contrib = (lane <= fp) ? (int)(sv & 0x3fffffffu) : 0;
#pragma unroll
                    for (int o = 16; o > 0; o >>= 1)
                        contrib += __shfl_down_sync(0xffffffffu, contrib, o);
                    running += __shfl_sync(0xffffffffu, contrib, 0);
                    break;
                } else {
                    int contrib = (int)(sv & 0x3fffffffu);
#pragma unroll
                    for (int o = 16; o > 0; o >>= 1)
                        contrib += __shfl_down_sync(0xffffffffu, contrib, o);
                    running += __shfl_sync(0xffffffffu, contrib, 0);
                    j -= 32;
                }
            }
        }
        if (lane == 0) {
            s_excl = running;
            if (b > 0) {
                // publish prefix = running + block_total (recompute from wsum[7] path not
                // available here; read aggregate we stored)
                unsigned my = atomicAdd(&g_state[b], 0u);
                int total = (int)(my & 0x3fffffffu);
                __threadfence();
                atomicExch(&g_state[b], (2u << 30) | (unsigned)(running + total));
            }
        }
    }
    __syncthreads();

    if (i < N_NODES) {
        int o = s_excl + wsum[w] + s - v;  // exclusive within block + block offset
        g_off[i] = o;
        g_cur[i] = o;
    }
    if (b == 0 && tid == 0) g_off[N_NODES] = N_EDGES;
}

__global__ void k_scatter(const void* __restrict__ ei) {
    int e = blockIdx.x * blockDim.x + threadIdx.x;
    if (e < N_EDGES) {
        int src = edge_at(ei, (size_t)e);
        int dst = edge_at(ei, (size_t)N_EDGES + e);
        int pos = atomicAdd(&g_cur[dst], 1);
        g_col[pos] = src;
    }
}

// ---------------- GEMM (tensor cores): U = fp16( dinv .* (A @ W) ) ----------------
// A: [N_NODES, 128] row-major (fp32 if CVT else fp16). W: [128, NCOLS] fp16.
// U: [N_NODES, NCOLS] fp16. 256 threads (8 warps), M-tile 128 (16 rows/warp).
template <int NCOLS, bool CVT>
__global__ void k_wgemm(const void* __restrict__ Ain, const __half* __restrict__ Wh,
                        __half* __restrict__ U) {
    extern __shared__ __align__(16) char smem_raw[];
    const int LDA = 136;          // 128 + 8 halves padding
    const int LDB = NCOLS + 8;
    __half* As = (__half*)smem_raw;              // 128 x LDA
    __half* Ws = (__half*)smem_raw + 128 * LDA;  // 128 x LDB
    float* stage = (float*)smem_raw;             // reused after mainloop

    int tid = threadIdx.x;
    int warp = tid >> 5, lane = tid & 31;
    int row0 = blockIdx.x * 128;

    // load A tile (128 rows x 128 halves), 8 halves per slot
    for (int i = tid; i < 128 * 16; i += 256) {
        int r = i >> 4, c8 = i & 15;
        int row = row0 + r;
        uint4 v = make_uint4(0u, 0u, 0u, 0u);
        if (row < N_NODES) {
            if (CVT) {
                const float4* A32 = (const float4*)Ain;
                float4 va = A32[(size_t)row * 32 + c8 * 2];
                float4 vb = A32[(size_t)row * 32 + c8 * 2 + 1];
                __half2 h0 = __floats2half2_rn(va.x, va.y);
                __half2 h1 = __floats2half2_rn(va.z, va.w);
                __half2 h2 = __floats2half2_rn(vb.x, vb.y);
                __half2 h3 = __floats2half2_rn(vb.z, vb.w);
                v.x = *(unsigned*)&h0; v.y = *(unsigned*)&h1;
                v.z = *(unsigned*)&h2; v.w = *(unsigned*)&h3;
            } else {
                v = *(const uint4*)&((const __half*)Ain)[(size_t)row * 128 + c8 * 8];
            }
        }
        *(uint4*)&As[r * LDA + c8 * 8] = v;
    }
    // load W tile (128 x NCOLS)
    for (int i = tid; i < 128 * (NCOLS / 8); i += 256) {
        int r = i / (NCOLS / 8), c8 = i % (NCOLS / 8);
        *(uint4*)&Ws[r * LDB + c8 * 8] = *(const uint4*)&Wh[(size_t)r * NCOLS + c8 * 8];
    }
    __syncthreads();

    const int NF = NCOLS / 16;
    wmma::fragment<wmma::accumulator, 16, 16, 16, float> acc[NF];
#pragma unroll
    for (int n = 0; n < NF; n++) wmma::fill_fragment(acc[n], 0.0f);

#pragma unroll
    for (int k = 0; k < 8; k++) {
        wmma::fragment<wmma::matrix_a, 16, 16, 16, __half, wmma::row_major> a;
        wmma::load_matrix_sync(a, &As[(warp * 16) * LDA + k * 16], LDA);
#pragma unroll
        for (int n = 0; n < NF; n++) {
            wmma::fragment<wmma::matrix_b, 16, 16, 16, __half, wmma::row_major> b;
            wmma::load_matrix_sync(b, &Ws[(k * 16) * LDB + n * 16], LDB);
            wmma::mma_sync(acc[n], a, b, acc[n]);
        }
    }
    __syncthreads();  // done with As/Ws; reuse as stage

    // epilogue: stage fp32 frag, scale by dinv[row], pack fp16, 16B stores
    float* wst = stage + warp * (16 * 20);
    int r = lane >> 1, c0 = (lane & 1) * 8;
    int row = row0 + warp * 16 + r;
    float d = (row < N_NODES) ? g_dinv[row] : 0.0f;
#pragma unroll
    for (int n = 0; n < NF; n++) {
        wmma::store_matrix_sync(wst, acc[n], 20, wmma::mem_row_major);
        __syncwarp();
        if (row < N_NODES) {
            const float* src = wst + r * 20 + c0;
            __half2 h0 = __floats2half2_rn(src[0] * d, src[1] * d);
            __half2 h1 = __floats2half2_rn(src[2] * d, src[3] * d);
            __half2 h2 = __floats2half2_rn(src[4] * d, src[5] * d);
            __half2 h3 = __floats2half2_rn(src[6] * d, src[7] * d);
            uint4 st;
            st.x = *(unsigned*)&h0; st.y = *(unsigned*)&h1;
            st.z = *(unsigned*)&h2; st.w = *(unsigned*)&h3;
            *(uint4*)&U[(size_t)row * NCOLS + n * 16 + c0] = st;
        }
        __syncwarp();
    }
}

// ---------------- aggregation (D=128): h[i] = fp16( relu( dinv[i]*(sum u[src] + u[i]) + b ) ) ----------------
__global__ void k_agg128(const __half* __restrict__ U, const float* __restrict__ bias,
                         __half* __restrict__ out) {
    int gw = (blockIdx.x * blockDim.x + threadIdx.x) >> 5;
    int lane = threadIdx.x & 31;
    if (gw >= N_NODES) return;
    const uint2* U2 = (const uint2*)U;

    uint2 raw = U2[(size_t)gw * 32 + lane];  // self term
    float2 f0 = __half22float2(*(__half2*)&raw.x);
    float2 f1 = __half22float2(*(__half2*)&raw.y);
    float ax = f0.x, ay = f0.y, az = f1.x, aw = f1.y;

    int e = g_off[gw];
    int e1 = g_off[gw + 1];
    for (; e + 3 < e1; e += 4) {
        int s0 = g_col[e], s1 = g_col[e + 1], s2 = g_col[e + 2], s3 = g_col[e + 3];
        uint2 r0 = U2[(size_t)s0 * 32 + lane];
        uint2 r1 = U2[(size_t)s1 * 32 + lane];
        uint2 r2 = U2[(size_t)s2 * 32 + lane];
        uint2 r3 = U2[(size_t)s3 * 32 + lane];
        float2 a0 = __half22float2(*(__half2*)&r0.x), b0 = __half22float2(*(__half2*)&r0.y);
        float2 a1 = __half22float2(*(__half2*)&r1.x), b1 = __half22float2(*(__half2*)&r1.y);
        float2 a2 = __half22float2(*(__half2*)&r2.x), b2 = __half22float2(*(__half2*)&r2.y);
        float2 a3 = __half22float2(*(__half2*)&r3.x), b3 = __half22float2(*(__half2*)&r3.y);
        ax += (a0.x + a1.x) + (a2.x + a3.x);
        ay += (a0.y + a1.y) + (a2.y + a3.y);
        az += (b0.x + b1.x) + (b2.x + b3.x);
        aw += (b0.y + b1.y) + (b2.y + b3.y);
    }
    for (; e < e1; e++) {
        int s0 = g_col[e];
        uint2 r0 = U2[(size_t)s0 * 32 + lane];
        float2 a0 = __half22float2(*(__half2*)&r0.x), b0 = __half22float2(*(__half2*)&r0.y);
        ax += a0.x; ay += a0.y; az += b0.x; aw += b0.y;
    }

    float d = g_dinv[gw];
    float4 b4 = *(const float4*)&bias[lane * 4];
    float ox = fmaxf(fmaf(ax, d, b4.x), 0.f);
    float oy = fmaxf(fmaf(ay, d, b4.y), 0.f);
    float oz = fmaxf(fmaf(az, d, b4.z), 0.f);
    float ow = fmaxf(fmaf(aw, d, b4.w), 0.f);
    __half2 p01 = __floats2half2_rn(ox, oy);
    __half2 p23 = __floats2half2_rn(oz, ow);
    uint2 st; st.x = *(unsigned*)&p01; st.y = *(unsigned*)&p23;
    ((uint2*)out)[(size_t)gw * 32 + lane] = st;
}

// ---------------- aggregation (D=64): final layer, fp32 out, no relu ----------------
__global__ void k_agg64(const __half* __restrict__ U, const float* __restrict__ bias,
                        float* __restrict__ out) {
    int gw = (blockIdx.x * blockDim.x + threadIdx.x) >> 5;
    int lane = threadIdx.x & 31;
    if (gw >= N_NODES) return;
    const unsigned* U1 = (const unsigned*)U;

    unsigned raw = U1[(size_t)gw * 32 + lane];
    float2 acc = __half22float2(*(__half2*)&raw);

    int e = g_off[gw];
    int e1 = g_off[gw + 1];
    for (; e + 3 < e1; e += 4) {
        int s0 = g_col[e], s1 = g_col[e + 1], s2 = g_col[e + 2], s3 = g_col[e + 3];
        unsigned r0 = U1[(size_t)s0 * 32 + lane];
        unsigned r1 = U1[(size_t)s1 * 32 + lane];
        unsigned r2 = U1[(size_t)s2 * 32 + lane];
        unsigned r3 = U1[(size_t)s3 * 32 + lane];
        float2 a0 = __half22float2(*(__half2*)&r0);
        float2 a1 = __half22float2(*(__half2*)&r1);
        float2 a2 = __half22float2(*(__half2*)&r2);
        float2 a3 = __half22float2(*(__half2*)&r3);
        acc.x += (a0.x + a1.x) + (a2.x + a3.x);
        acc.y += (a0.y + a1.y) + (a2.y + a3.y);
    }
    for (; e < e1; e++) {
        unsigned r0 = U1[(size_t)g_col[e] * 32 + lane];
        float2 a0 = __half22float2(*(__half2*)&r0);
        acc.x += a0.x; acc.y += a0.y;
    }

    float d = g_dinv[gw];
    float2 b2 = *(const float2*)&bias[lane * 2];
    float2 o;
    o.x = fmaf(acc.x, d, b2.x);
    o.y = fmaf(acc.y, d, b2.y);
    ((float2*)out)[(size_t)gw * 32 + lane] = o;
}

// ---------------- launch ----------------
extern "C" void kernel_launch(void* const* d_in, const int* in_sizes, int n_in,
                              void* d_out, int out_size) {
    const float* x  = (const float*)d_in[0];
    const void*  ei = d_in[1];
    const float* W1 = (const float*)d_in[2];
    const float* b1 = (const float*)d_in[3];
    const float* W2 = (const float*)d_in[4];
    const float* b2 = (const float*)d_in[5];
    const float* W3 = (const float*)d_in[6];
    const float* b3 = (const float*)d_in[7];
    float* out = (float*)d_out;

    __half *bufU, *bufH, *Wh;
    unsigned* zero;
    cudaGetSymbolAddress((void**)&bufU, g_bufU);
    cudaGetSymbolAddress((void**)&bufH, g_bufH);
    cudaGetSymbolAddress((void**)&Wh, g_Wh);
    cudaGetSymbolAddress((void**)&zero, g_zero);

    const int TB = 256;
    const int SMEM128 = (128 * 136 + 128 * 136) * 2;  // 69632
    const int SMEM64  = (128 * 136 + 128 * 72) * 2;   // 53248
    cudaFuncSetAttribute(k_wgemm<128, true>,  cudaFuncAttributeMaxDynamicSharedMemorySize, SMEM128);
    cudaFuncSetAttribute(k_wgemm<128, false>, cudaFuncAttributeMaxDynamicSharedMemorySize, SMEM128);
    cudaFuncSetAttribute(k_wgemm<64, false>,  cudaFuncAttributeMaxDynamicSharedMemorySize, SMEM64);

    // prep: dtype detect + W convert | zero counts+scan state | count | scan | scatter
    k_detect_cvtW<<<161, TB>>>((const long long*)ei, W1, W2, W3);
    cudaMemsetAsync(zero, 0, (N_NODES + NBLK) * sizeof(unsigned));
    k_count<<<(N_EDGES + TB - 1) / TB, TB>>>(ei);
    k_scan<<<NBLK, TB>>>();
    k_scatter<<<(N_EDGES + TB - 1) / TB, TB>>>(ei);

    int gemm_blocks = (N_NODES + 127) / 128;
    int agg_blocks = (N_NODES * 32 + TB - 1) / TB;

    // layer 1 (GEMM converts fp32 x on the fly)
    k_wgemm<128, true><<<gemm_blocks, TB, SMEM128>>>(x, Wh, bufU);
    k_agg128<<<agg_blocks, TB>>>(bufU, b1, bufH);
    // layer 2
    k_wgemm<128, false><<<gemm_blocks, TB, SMEM128>>>(bufH, Wh + 16384, bufU);
    k_agg128<<<agg_blocks, TB>>>(bufU, b2, bufH);
    // layer 3 (no relu), D_out = 64
    k_wgemm<64, false><<<gemm_blocks, TB, SMEM64>>>(bufH, Wh + 32768, bufU);
    k_agg64<<<agg_blocks, TB>>>(bufU, b3, out);
}

// round 6
// speedup vs baseline: 2.3764x; 1.0501x over previous
#include <cuda_runtime.h>
#include <cuda_fp16.h>
#include <mma.h>
#include <cstddef>

using namespace nvcuda;

#define N_NODES 50000
#define N_EDGES 800000
#define NBLK 196   // ceil(50000/256)

// ---------------- scratch (static device arrays; no allocation) ----------------
__device__ __align__(16) __half g_bufU[N_NODES * 128];  // GEMM output (gathered)
__device__ __align__(16) __half g_bufH[N_NODES * 128];  // activations (GEMM input)
__device__ __align__(16) __half g_Wh[40960];            // W1(16384) W2(16384) W3(8192) fp16
__device__ float g_dinv[N_NODES];
// contiguous zero region: [0, N_NODES) = counts, [N_NODES, N_NODES+NBLK) = scan state
__device__ unsigned g_zero[N_NODES + NBLK];
__device__ int   g_off[N_NODES + 1];
__device__ int   g_cur[N_NODES];
__device__ int   g_col[N_EDGES];
__device__ int   g_is32;

#define g_cnt   ((int*)g_zero)
#define g_state (g_zero + N_NODES)

// edge accessor: handles int32 vs int64 storage (flag set by k_detect_cvtW)
__device__ __forceinline__ int edge_at(const void* ei, size_t idx) {
    if (g_is32) return ((const int*)ei)[idx];
    return (int)((const long long*)ei)[idx];
}

// ---------------- fused: dtype detection (block 0) + W fp32->fp16 (blocks 1..160) ----------------
__global__ void k_detect_cvtW(const long long* __restrict__ ei64,
                              const float* __restrict__ W1,
                              const float* __restrict__ W2,
                              const float* __restrict__ W3) {
    if (blockIdx.x == 0) {
        __shared__ int flag;
        if (threadIdx.x == 0) flag = 0;
        __syncthreads();
        if (threadIdx.x < 64) {
            long long v = ei64[threadIdx.x];
            if (v < 0 || v >= N_NODES) flag = 1;
        }
        __syncthreads();
        if (threadIdx.x == 0) g_is32 = flag;
    } else {
        int i = (blockIdx.x - 1) * 256 + threadIdx.x;
        if (i < 40960) {
            float v;
            if (i < 16384) v = W1[i];
            else if (i < 32768) v = W2[i - 16384];
            else v = W3[i - 32768];
            g_Wh[i] = __float2half_rn(v);
        }
    }
}

// ---------------- graph prep ----------------
__global__ void k_count(const void* __restrict__ ei) {
    int e = blockIdx.x * blockDim.x + threadIdx.x;
    if (e < N_EDGES) {
        int dst = edge_at(ei, (size_t)N_EDGES + e);
        atomicAdd(&g_cnt[dst], 1);
    }
}

// single-pass decoupled-lookback exclusive scan of g_cnt -> g_off/g_cur (+ fused dinv)
// state word: status(2b)<<30 | value(30b). status: 0 invalid, 1 aggregate, 2 prefix.
__global__ void k_scan() {
    __shared__ int wsum[8];
    __shared__ int s_excl;
    int tid = threadIdx.x;
    int lane = tid & 31, w = tid >> 5;
    int b = blockIdx.x;
    int i = b * 256 + tid;

    int v = (i < N_NODES) ? g_cnt[i] : 0;
    if (i < N_NODES) g_dinv[i] = rsqrtf((float)v + 1.0f);  // +1 = self loop

    // warp inclusive scan
    int s = v;
#pragma unroll
    for (int o = 1; o < 32; o <<= 1) {
        int t = __shfl_up_sync(0xffffffffu, s, o);
        if (lane >= o) s += t;
    }
    if (lane == 31) wsum[w] = s;
    __syncthreads();
    if (tid == 0) {
        int run = 0;
#pragma unroll
        for (int k = 0; k < 8; k++) { int t = wsum[k]; wsum[k] = run; run += t; }
        __threadfence();
        unsigned st = (b == 0 ? 2u : 1u) << 30 | (unsigned)run;
        atomicExch(&g_state[b], st);
    }
    __syncthreads();

    // warp 0: lookback for exclusive block prefix
    if (w == 0) {
        int running = 0;
        if (b > 0) {
            int j = b - 1;
            while (true) {
                int idx = j - lane;
                unsigned sv;
                if (idx >= 0) {
                    sv = atomicAdd(&g_state[idx], 0u);  // strong read
                } else {
                    sv = 2u << 30;  // virtual prefix 0
                }
                unsigned stt = sv >> 30;
                unsigned ball = __ballot_sync(0xffffffffu, stt >= 1u);
                if (ball != 0xffffffffu) continue;  // some invalid -> retry window
                unsigned pball = __ballot_sync(0xffffffffu, stt == 2u);
                if (pball) {
                    int fp = __ffs(pball) - 1;  // nearest prefix
                    int contrib = (lane <= fp) ? (int)(sv & 0x3fffffffu) : 0;
#pragma unroll
                    for (int o = 16; o > 0; o >>= 1)
                        contrib += __shfl_down_sync(0xffffffffu, contrib, o);
                    running += __shfl_sync(0xffffffffu, contrib, 0);
                    break;
                } else {
                    int contrib = (int)(sv & 0x3fffffffu);
#pragma unroll
                    for (int o = 16; o > 0; o >>= 1)
                        contrib += __shfl_down_sync(0xffffffffu, contrib, o);
                    running += __shfl_sync(0xffffffffu, contrib, 0);
                    j -= 32;
                }
            }
        }
        if (lane == 0) {
            s_excl = running;
            if (b > 0) {
                unsigned my = atomicAdd(&g_state[b], 0u);
                int total = (int)(my & 0x3fffffffu);
                __threadfence();
                atomicExch(&g_state[b], (2u << 30) | (unsigned)(running + total));
            }
        }
    }
    __syncthreads();

    if (i < N_NODES) {
        int o = s_excl + wsum[w] + s - v;
        g_off[i] = o;
        g_cur[i] = o;
    }
    if (b == 0 && tid == 0) g_off[N_NODES] = N_EDGES;
}

__global__ void k_scatter(const void* __restrict__ ei) {
    int e = blockIdx.x * blockDim.x + threadIdx.x;
    if (e < N_EDGES) {
        int src = edge_at(ei, (size_t)e);
        int dst = edge_at(ei, (size_t)N_EDGES + e);
        int pos = atomicAdd(&g_cur[dst], 1);
        g_col[pos] = src;
    }
}

// ---------------- GEMM (tensor cores): U = fp16( [dinv .*] (A @ W) ) ----------------
// A: [N_NODES, 128] row-major (fp32 if CVT else fp16). W: [128, NCOLS] fp16.
// U: [N_NODES, NCOLS] fp16. 256 threads (8 warps), M-tile 128 (16 rows/warp).
// SCALE=false: no dinv in epilogue (used for layer 1 so GEMM is graph-independent).
template <int NCOLS, bool CVT, bool SCALE>
__global__ void k_wgemm(const void* __restrict__ Ain, const __half* __restrict__ Wh,
                        __half* __restrict__ U) {
    extern __shared__ __align__(16) char smem_raw[];
    const int LDA = 136;
    const int LDB = NCOLS + 8;
    __half* As = (__half*)smem_raw;              // 128 x LDA
    __half* Ws = (__half*)smem_raw + 128 * LDA;  // 128 x LDB
    float* stage = (float*)smem_raw;             // reused after mainloop

    int tid = threadIdx.x;
    int warp = tid >> 5, lane = tid & 31;
    int row0 = blockIdx.x * 128;

    for (int i = tid; i < 128 * 16; i += 256) {
        int r = i >> 4, c8 = i & 15;
        int row = row0 + r;
        uint4 v = make_uint4(0u, 0u, 0u, 0u);
        if (row < N_NODES) {
            if (CVT) {
                const float4* A32 = (const float4*)Ain;
                float4 va = A32[(size_t)row * 32 + c8 * 2];
                float4 vb = A32[(size_t)row * 32 + c8 * 2 + 1];
                __half2 h0 = __floats2half2_rn(va.x, va.y);
                __half2 h1 = __floats2half2_rn(va.z, va.w);
                __half2 h2 = __floats2half2_rn(vb.x, vb.y);
                __half2 h3 = __floats2half2_rn(vb.z, vb.w);
                v.x = *(unsigned*)&h0; v.y = *(unsigned*)&h1;
                v.z = *(unsigned*)&h2; v.w = *(unsigned*)&h3;
            } else {
                v = *(const uint4*)&((const __half*)Ain)[(size_t)row * 128 + c8 * 8];
            }
        }
        *(uint4*)&As[r * LDA + c8 * 8] = v;
    }
    for (int i = tid; i < 128 * (NCOLS / 8); i += 256) {
        int r = i / (NCOLS / 8), c8 = i % (NCOLS / 8);
        *(uint4*)&Ws[r * LDB + c8 * 8] = *(const uint4*)&Wh[(size_t)r * NCOLS + c8 * 8];
    }
    __syncthreads();

    const int NF = NCOLS / 16;
    wmma::fragment<wmma::accumulator, 16, 16, 16, float> acc[NF];
#pragma unroll
    for (int n = 0; n < NF; n++) wmma::fill_fragment(acc[n], 0.0f);

#pragma unroll
    for (int k = 0; k < 8; k++) {
        wmma::fragment<wmma::matrix_a, 16, 16, 16, __half, wmma::row_major> a;
        wmma::load_matrix_sync(a, &As[(warp * 16) * LDA + k * 16], LDA);
#pragma unroll
        for (int n = 0; n < NF; n++) {
            wmma::fragment<wmma::matrix_b, 16, 16, 16, __half, wmma::row_major> b;
            wmma::load_matrix_sync(b, &Ws[(k * 16) * LDB + n * 16], LDB);
            wmma::mma_sync(acc[n], a, b, acc[n]);
        }
    }
    __syncthreads();

    float* wst = stage + warp * (16 * 20);
    int r = lane >> 1, c0 = (lane & 1) * 8;
    int row = row0 + warp * 16 + r;
    float d = 1.0f;
    if (SCALE) d = (row < N_NODES) ? g_dinv[row] : 0.0f;
#pragma unroll
    for (int n = 0; n < NF; n++) {
        wmma::store_matrix_sync(wst, acc[n], 20, wmma::mem_row_major);
        __syncwarp();
        if (row < N_NODES) {
            const float* src = wst + r * 20 + c0;
            __half2 h0 = __floats2half2_rn(src[0] * d, src[1] * d);
            __half2 h1 = __floats2half2_rn(src[2] * d, src[3] * d);
            __half2 h2 = __floats2half2_rn(src[4] * d, src[5] * d);
            __half2 h3 = __floats2half2_rn(src[6] * d, src[7] * d);
            uint4 st;
            st.x = *(unsigned*)&h0; st.y = *(unsigned*)&h1;
            st.z = *(unsigned*)&h2; st.w = *(unsigned*)&h3;
            *(uint4*)&U[(size_t)row * NCOLS + n * 16 + c0] = st;
        }
        __syncwarp();
    }
}

// ---------------- aggregation (D=128) ----------------
// SRCSCALE: U is unscaled (layer 1); multiply each gathered row by dinv[src].
// out = fp16( relu( dinv[i]*acc + b ) )
template <bool SRCSCALE>
__global__ void k_agg128(const __half* __restrict__ U, const float* __restrict__ bias,
                         __half* __restrict__ out) {
    int gw = (blockIdx.x * blockDim.x + threadIdx.x) >> 5;
    int lane = threadIdx.x & 31;
    if (gw >= N_NODES) return;
    const uint2* U2 = (const uint2*)U;

    float dself = g_dinv[gw];
    uint2 raw = U2[(size_t)gw * 32 + lane];  // self term
    float2 f0 = __half22float2(*(__half2*)&raw.x);
    float2 f1 = __half22float2(*(__half2*)&raw.y);
    float sw = SRCSCALE ? dself : 1.0f;
    float ax = f0.x * sw, ay = f0.y * sw, az = f1.x * sw, aw = f1.y * sw;

    int e = g_off[gw];
    int e1 = g_off[gw + 1];
    for (; e + 3 < e1; e += 4) {
        int s0 = g_col[e], s1 = g_col[e + 1], s2 = g_col[e + 2], s3 = g_col[e + 3];
        uint2 r0 = U2[(size_t)s0 * 32 + lane];
        uint2 r1 = U2[(size_t)s1 * 32 + lane];
        uint2 r2 = U2[(size_t)s2 * 32 + lane];
        uint2 r3 = U2[(size_t)s3 * 32 + lane];
        float2 a0 = __half22float2(*(__half2*)&r0.x), b0 = __half22float2(*(__half2*)&r0.y);
        float2 a1 = __half22float2(*(__half2*)&r1.x), b1 = __half22float2(*(__half2*)&r1.y);
        float2 a2 = __half22float2(*(__half2*)&r2.x), b2 = __half22float2(*(__half2*)&r2.y);
        float2 a3 = __half22float2(*(__half2*)&r3.x), b3 = __half22float2(*(__half2*)&r3.y);
        if (SRCSCALE) {
            float d0 = g_dinv[s0], d1 = g_dinv[s1], d2 = g_dinv[s2], d3 = g_dinv[s3];
            ax = fmaf(a0.x, d0, fmaf(a1.x, d1, fmaf(a2.x, d2, fmaf(a3.x, d3, ax))));
            ay = fmaf(a0.y, d0, fmaf(a1.y, d1, fmaf(a2.y, d2, fmaf(a3.y, d3, ay))));
            az = fmaf(b0.x, d0, fmaf(b1.x, d1, fmaf(b2.x, d2, fmaf(b3.x, d3, az))));
            aw = fmaf(b0.y, d0, fmaf(b1.y, d1, fmaf(b2.y, d2, fmaf(b3.y, d3, aw))));
        } else {
            ax += (a0.x + a1.x) + (a2.x + a3.x);
            ay += (a0.y + a1.y) + (a2.y + a3.y);
            az += (b0.x + b1.x) + (b2.x + b3.x);
            aw += (b0.y + b1.y) + (b2.y + b3.y);
        }
    }
    for (; e < e1; e++) {
        int s0 = g_col[e];
        uint2 r0 = U2[(size_t)s0 * 32 + lane];
        float2 a0 = __half22float2(*(__half2*)&r0.x), b0 = __half22float2(*(__half2*)&r0.y);
        if (SRCSCALE) {
            float d0 = g_dinv[s0];
            ax = fmaf(a0.x, d0, ax); ay = fmaf(a0.y, d0, ay);
            az = fmaf(b0.x, d0, az); aw = fmaf(b0.y, d0, aw);
        } else {
            ax += a0.x; ay += a0.y; az += b0.x; aw += b0.y;
        }
    }

    float4 b4 = *(const float4*)&bias[lane * 4];
    float ox = fmaxf(fmaf(ax, dself, b4.x), 0.f);
    float oy = fmaxf(fmaf(ay, dself, b4.y), 0.f);
    float oz = fmaxf(fmaf(az, dself, b4.z), 0.f);
    float ow = fmaxf(fmaf(aw, dself, b4.w), 0.f);
    __half2 p01 = __floats2half2_rn(ox, oy);
    __half2 p23 = __floats2half2_rn(oz, ow);
    uint2 st; st.x = *(unsigned*)&p01; st.y = *(unsigned*)&p23;
    ((uint2*)out)[(size_t)gw * 32 + lane] = st;
}

// ---------------- aggregation (D=64): final layer, fp32 out, no relu ----------------
__global__ void k_agg64(const __half* __restrict__ U, const float* __restrict__ bias,
                        float* __restrict__ out) {
    int gw = (blockIdx.x * blockDim.x + threadIdx.x) >> 5;
    int lane = threadIdx.x & 31;
    if (gw >= N_NODES) return;
    const unsigned* U1 = (const unsigned*)U;

    unsigned raw = U1[(size_t)gw * 32 + lane];
    float2 acc = __half22float2(*(__half2*)&raw);

    int e = g_off[gw];
    int e1 = g_off[gw + 1];
    for (; e + 3 < e1; e += 4) {
        int s0 = g_col[e], s1 = g_col[e + 1], s2 = g_col[e + 2], s3 = g_col[e + 3];
        unsigned r0 = U1[(size_t)s0 * 32 + lane];
        unsigned r1 = U1[(size_t)s1 * 32 + lane];
        unsigned r2 = U1[(size_t)s2 * 32 + lane];
        unsigned r3 = U1[(size_t)s3 * 32 + lane];
        float2 a0 = __half22float2(*(__half2*)&r0);
        float2 a1 = __half22float2(*(__half2*)&r1);
        float2 a2 = __half22float2(*(__half2*)&r2);
        float2 a3 = __half22float2(*(__half2*)&r3);
        acc.x += (a0.x + a1.x) + (a2.x + a3.x);
        acc.y += (a0.y + a1.y) + (a2.y + a3.y);
    }
    for (; e < e1; e++) {
        unsigned r0 = U1[(size_t)g_col[e] * 32 + lane];
        float2 a0 = __half22float2(*(__half2*)&r0);
        acc.x += a0.x; acc.y += a0.y;
    }

    float d = g_dinv[gw];
    float2 b2 = *(const float2*)&bias[lane * 2];
    float2 o;
    o.x = fmaf(acc.x, d, b2.x);
    o.y = fmaf(acc.y, d, b2.y);
    ((float2*)out)[(size_t)gw * 32 + lane] = o;
}

// ---------------- launch ----------------
extern "C" void kernel_launch(void* const* d_in, const int* in_sizes, int n_in,
                              void* d_out, int out_size) {
    const float* x  = (const float*)d_in[0];
    const void*  ei = d_in[1];
    const float* W1 = (const float*)d_in[2];
    const float* b1 = (const float*)d_in[3];
    const float* W2 = (const float*)d_in[4];
    const float* b2 = (const float*)d_in[5];
    const float* W3 = (const float*)d_in[6];
    const float* b3 = (const float*)d_in[7];
    float* out = (float*)d_out;

    __half *bufU, *bufH, *Wh;
    unsigned* zero;
    cudaGetSymbolAddress((void**)&bufU, g_bufU);
    cudaGetSymbolAddress((void**)&bufH, g_bufH);
    cudaGetSymbolAddress((void**)&Wh, g_Wh);
    cudaGetSymbolAddress((void**)&zero, g_zero);

    // side stream + events for fork/join (created once; host-side only)
    static cudaStream_t s1 = nullptr;
    static cudaEvent_t evFork = nullptr, evJoin = nullptr;
    if (s1 == nullptr) {
        cudaStreamCreateWithFlags(&s1, cudaStreamNonBlocking);
        cudaEventCreateWithFlags(&evFork, cudaEventDisableTiming);
        cudaEventCreateWithFlags(&evJoin, cudaEventDisableTiming);
    }

    const int TB = 256;
    const int SMEM128 = (128 * 136 + 128 * 136) * 2;  // 69632
    const int SMEM64  = (128 * 136 + 128 * 72) * 2;   // 53248
    cudaFuncSetAttribute(k_wgemm<128, true, false>, cudaFuncAttributeMaxDynamicSharedMemorySize, SMEM128);
    cudaFuncSetAttribute(k_wgemm<128, false, true>, cudaFuncAttributeMaxDynamicSharedMemorySize, SMEM128);
    cudaFuncSetAttribute(k_wgemm<64, false, true>,  cudaFuncAttributeMaxDynamicSharedMemorySize, SMEM64);

    int gemm_blocks = (N_NODES + 127) / 128;
    int agg_blocks = (N_NODES * 32 + TB - 1) / TB;

    // ---- fork: s0 = graph prep, s1 = layer-1 GEMM (graph-independent) ----
    k_detect_cvtW<<<161, TB>>>((const long long*)ei, W1, W2, W3);
    cudaEventRecord(evFork, 0);
    cudaStreamWaitEvent(s1, evFork, 0);

    // s1: layer-1 GEMM, unscaled epilogue (dinv applied in agg)
    k_wgemm<128, true, false><<<gemm_blocks, TB, SMEM128, s1>>>(x, Wh, bufU);

    // s0: graph prep chain
    cudaMemsetAsync(zero, 0, (N_NODES + NBLK) * sizeof(unsigned));
    k_count<<<(N_EDGES + TB - 1) / TB, TB>>>(ei);
    k_scan<<<NBLK, TB>>>();
    k_scatter<<<(N_EDGES + TB - 1) / TB, TB>>>(ei);

    // join
    cudaEventRecord(evJoin, s1);
    cudaStreamWaitEvent(0, evJoin, 0);

    // layer 1 agg (applies dinv[src] and dinv[dst])
    k_agg128<true><<<agg_blocks, TB>>>(bufU, b1, bufH);
    // layer 2
    k_wgemm<128, false, true><<<gemm_blocks, TB, SMEM128>>>(bufH, Wh + 16384, bufU);
    k_agg128<false><<<agg_blocks, TB>>>(bufU, b2, bufH);
    // layer 3 (no relu), D_out = 64
    k_wgemm<64, false, true><<<gemm_blocks, TB, SMEM64>>>(bufH, Wh + 32768, bufU);
    k_agg64<<<agg_blocks, TB>>>(bufU, b3, out);
}